// round 5
// baseline (speedup 1.0000x reference)
#include <cuda_runtime.h>
#include <cuda_fp16.h>
#include <mma.h>
#include <math.h>
#include <stdint.h>

using namespace nvcuda;

#define B_WIN  4096
#define NT     49
#define CDIM   256
#define HEADS  8
#define HDIM   32
#define KQKV   768
#define MROWS  (B_WIN * NT)          /* 200704 = 128*1568 */
#define SCALE_F 0.17677669529663687f /* 32^-0.5 */

/* -------- scratch (allocation-free: __device__ globals) -------- */
__device__ __half g_xh[(size_t)MROWS * CDIM];    /* x in fp16            */
__device__ __half g_qkvh[(size_t)MROWS * KQKV];  /* qkv in fp16          */
__device__ __half g_oh[(size_t)MROWS * CDIM];    /* attn out in fp16     */
__device__ __half g_wh[(size_t)KQKV * CDIM];     /* qkv_w fp16           */
__device__ __half g_pwh[(size_t)CDIM * CDIM];    /* proj_w fp16          */

/* -------- cp.async helpers -------- */
__device__ __forceinline__ void cp_async16(void* smem_dst, const void* gmem_src) {
    unsigned sa = (unsigned)__cvta_generic_to_shared(smem_dst);
    asm volatile("cp.async.cg.shared.global [%0], [%1], 16;\n" :: "r"(sa), "l"(gmem_src));
}
__device__ __forceinline__ void cp_commit() {
    asm volatile("cp.async.commit_group;\n" ::: "memory");
}
template <int N>
__device__ __forceinline__ void cp_wait() {
    asm volatile("cp.async.wait_group %0;\n" :: "n"(N) : "memory");
}

/* =====================================================================
 * fp32 -> fp16 convert (vectorized, n % 4 == 0)
 * ===================================================================*/
__global__ __launch_bounds__(256) void f2h_kernel(
    const float* __restrict__ in, __half* __restrict__ out, int n)
{
    int i = (blockIdx.x * 256 + threadIdx.x) * 4;
    if (i < n) {
        float4 v = *(const float4*)&in[i];
        *(half2*)&out[i]     = __floats2half2_rn(v.x, v.y);
        *(half2*)&out[i + 2] = __floats2half2_rn(v.z, v.w);
    }
}

/* =====================================================================
 * GEMM v4 (fp16 HMMA): C[m,n] = sum_k A[m,k]*W[n,k] + bias[n]
 * Block 128x128, BK=32, 3-stage cp.async pipeline (wait_group 2),
 * 256 thr = 8 warps (4M x 2N), warp tile 32x64, m16n16k16 fp16->fp32.
 * OUT_HALF=1: stage + convert to fp16.  OUT_HALF=0: direct fp32 store.
 * Requires M%128==0, N%128==0, K%32==0.
 * ===================================================================*/
#define H4_TILE  (128 * 40)               /* halves per operand tile   */
#define H4_STAGE (2 * H4_TILE)            /* halves per (A+B) stage    */
#define GEMMH_SMEM (3 * H4_STAGE * 2 + 16 * 132 * 4 + 128)

template <int OUT_HALF>
__global__ __launch_bounds__(256) void gemm_h_kernel(
    const __half* __restrict__ A, const __half* __restrict__ W,
    const float* __restrict__ bias, void* __restrict__ Cv,
    int Nld, int K)
{
    extern __shared__ char smem_raw[];
    __half* Ah    = (__half*)smem_raw;                       /* 3 stages */
    float*  btile = (float*)(smem_raw + 3 * H4_STAGE * 2);   /* 16x132   */

    const int tid  = threadIdx.x;
    const int warp = tid >> 5;
    const int wm   = warp >> 1;  /* 0..3 along M */
    const int wn   = warp & 1;   /* 0..1 along N */
    const int m0   = blockIdx.y * 128;
    const int n0   = blockIdx.x * 128;
    const int nk   = K >> 5;

    const int cr = tid >> 2;       /* base row 0..63        */
    const int cc = tid & 3;        /* 16B chunk (8 halves)  */

    /* issue stages 0..2 */
#pragma unroll
    for (int st = 0; st < 3; st++) {
        if (st < nk) {
            int kc = st * 32;
#pragma unroll
            for (int i = 0; i < 2; i++) {
                int r = cr + i * 64;
                cp_async16(&Ah[st * H4_STAGE + r * 40 + cc * 8],
                           &A[(size_t)(m0 + r) * K + kc + cc * 8]);
                cp_async16(&Ah[st * H4_STAGE + H4_TILE + r * 40 + cc * 8],
                           &W[(size_t)(n0 + r) * K + kc + cc * 8]);
            }
        }
        cp_commit();
    }

    /* bias tile: 16 identical rows */
    for (int idx = tid; idx < 16 * 128; idx += 256) {
        int row = idx >> 7, col = idx & 127;
        btile[row * 132 + col] = bias[n0 + col];
    }
    __syncthreads();

    wmma::fragment<wmma::accumulator, 16, 16, 16, float> c[2][4];
#pragma unroll
    for (int j = 0; j < 4; j++) {
        wmma::load_matrix_sync(c[0][j], &btile[wn * 64 + j * 16], 132,
                               wmma::mem_row_major);
        c[1][j] = c[0][j];
    }

    for (int kt = 0; kt < nk; kt++) {
        cp_wait<2>();
        __syncthreads();
        const int st = kt % 3;
        const __half* Ab = Ah + st * H4_STAGE;
        const __half* Bb = Ab + H4_TILE;

#pragma unroll
        for (int ks = 0; ks < 2; ks++) {
            wmma::fragment<wmma::matrix_a, 16, 16, 16, __half, wmma::row_major> a[2];
#pragma unroll
            for (int i = 0; i < 2; i++)
                wmma::load_matrix_sync(a[i], &Ab[(wm * 32 + i * 16) * 40 + ks * 16], 40);
#pragma unroll
            for (int j = 0; j < 4; j++) {
                wmma::fragment<wmma::matrix_b, 16, 16, 16, __half, wmma::col_major> b;
                wmma::load_matrix_sync(b, &Bb[(wn * 64 + j * 16) * 40 + ks * 16], 40);
                wmma::mma_sync(c[0][j], a[0], b, c[0][j]);
                wmma::mma_sync(c[1][j], a[1], b, c[1][j]);
            }
        }
        __syncthreads();

        int kn = kt + 3;
        if (kn < nk) {
            int kc = kn * 32;
#pragma unroll
            for (int i = 0; i < 2; i++) {
                int r = cr + i * 64;
                cp_async16(&Ah[st * H4_STAGE + r * 40 + cc * 8],
                           &A[(size_t)(m0 + r) * K + kc + cc * 8]);
                cp_async16(&Ah[st * H4_STAGE + H4_TILE + r * 40 + cc * 8],
                           &W[(size_t)(n0 + r) * K + kc + cc * 8]);
            }
        }
        cp_commit();
    }

    if (OUT_HALF) {
        float* stg = (float*)smem_raw;   /* 128 x 132 floats over stages+btile */
        __syncthreads();
#pragma unroll
        for (int i = 0; i < 2; i++)
#pragma unroll
            for (int j = 0; j < 4; j++)
                wmma::store_matrix_sync(
                    &stg[(wm * 32 + i * 16) * 132 + wn * 64 + j * 16],
                    c[i][j], 132, wmma::mem_row_major);
        __syncthreads();
        __half* Ch = (__half*)Cv;
        for (int idx = tid; idx < 128 * 64; idx += 256) {
            int row = idx >> 6, cp2 = (idx & 63) << 1;
            half2 h = __floats2half2_rn(stg[row * 132 + cp2],
                                        stg[row * 132 + cp2 + 1]);
            *(half2*)&Ch[(size_t)(m0 + row) * Nld + n0 + cp2] = h;
        }
    } else {
        float* Cf = (float*)Cv;
#pragma unroll
        for (int i = 0; i < 2; i++)
#pragma unroll
            for (int j = 0; j < 4; j++)
                wmma::store_matrix_sync(
                    &Cf[(size_t)(m0 + wm * 32 + i * 16) * Nld + n0 + wn * 64 + j * 16],
                    c[i][j], Nld, wmma::mem_row_major);
    }
}

/* =====================================================================
 * Attention v4: one block per (window b, head h), 128 thr, 4 warps.
 * Warp-privatized: after S is staged, each warp owns rows 16w..16w+15
 * through bias/softmax/attn-write/P/O — only 2 __syncthreads total.
 * P tile (fp16) overlays the dead q/k buffer. Only V padding is zeroed;
 * q/k pad garbage is confined to discarded rows/cols (P cols>=49 are
 * explicitly zeroed so pad-NaN cannot reach O).
 * ===================================================================*/
__global__ __launch_bounds__(128) void attn_kernel(
    const __half* __restrict__ qkv, const float* __restrict__ mask,
    const float* __restrict__ bias_table, float* __restrict__ attn_out,
    __half* __restrict__ o_out)
{
    __shared__ __half qk[2 * 64 * 40];   /* q: [0,2560) halves, k: [2560,5120) */
    __shared__ __half vs[64 * 40];
    __shared__ float  ss[64 * 68];
    __shared__ float  biasS[176];
    __half* ps = qk;                     /* P overlay, stride 72 (4608 <= 5120) */

    const int tid  = threadIdx.x;
    const int warp = tid >> 5;
    const int lane = tid & 31;
    const int h    = blockIdx.x;
    const int b    = blockIdx.y;
    const int r0   = warp * 16;

    /* zero V pad rows 49..63; gather this head's bias column */
    {
        half2 z = __floats2half2_rn(0.f, 0.f);
        half2* v2 = (half2*)vs;
        for (int i = tid; i < 15 * 20; i += 128) v2[49 * 20 + i] = z;
    }
    for (int r = tid; r < 169; r += 128) biasS[r] = __ldg(&bias_table[r * HEADS + h]);

    /* load q/k/v (half2): 49 rows x 16 half2 */
    {
        const __half* base = qkv + (size_t)b * NT * KQKV + h * HDIM;
        half2* q2 = (half2*)qk;
        half2* k2 = (half2*)(qk + 2560);
        half2* v2 = (half2*)vs;
        for (int idx = tid; idx < NT * 16; idx += 128) {
            int n = idx >> 4, d2 = idx & 15;
            const half2* src = (const half2*)(base + (size_t)n * KQKV) + d2;
            q2[n * 20 + d2] = src[0];
            k2[n * 20 + d2] = src[128];   /* +256 halves */
            v2[n * 20 + d2] = src[256];   /* +512 halves */
        }
    }
    __syncthreads();

    /* S = Q K^T (warp rows r0..r0+15, all 64 cols), stage to ss */
    {
        wmma::fragment<wmma::accumulator, 16, 16, 16, float> sc[4];
#pragma unroll
        for (int j = 0; j < 4; j++) wmma::fill_fragment(sc[j], 0.0f);
#pragma unroll
        for (int ks = 0; ks < 2; ks++) {
            wmma::fragment<wmma::matrix_a, 16, 16, 16, __half, wmma::row_major> a;
            wmma::load_matrix_sync(a, &qk[r0 * 40 + ks * 16], 40);
#pragma unroll
            for (int j = 0; j < 4; j++) {
                wmma::fragment<wmma::matrix_b, 16, 16, 16, __half, wmma::col_major> bfr;
                wmma::load_matrix_sync(bfr, &qk[2560 + (j * 16) * 40 + ks * 16], 40);
                wmma::mma_sync(sc[j], a, bfr, sc[j]);
            }
        }
#pragma unroll
        for (int j = 0; j < 4; j++)
            wmma::store_matrix_sync(&ss[r0 * 68 + j * 16], sc[j], 68,
                                    wmma::mem_row_major);
    }
    __syncthreads();   /* all S staged; q/k buffer is now dead -> P overlay */

    /* ---- everything below is warp-private (rows r0..r0+15) ---- */

    /* bias + mask (valid rows/cols only) */
    {
        const float* mwin = mask + (size_t)(b & 63) * NT * NT;
        for (int idx = lane; idx < 16 * NT; idx += 32) {
            int r = idx / NT, m = idx - r * NT, n = r0 + r;
            if (n < NT) {
                int nh = n / 7, nw = n - nh * 7;
                int mh = m / 7, mw = m - mh * 7;
                int rel = (nh - mh + 6) * 13 + (nw - mw + 6);
                ss[n * 68 + m] = ss[n * 68 + m] * SCALE_F + biasS[rel] + mwin[n * NT + m];
            }
        }
    }
    __syncwarp();

    /* softmax: 2 threads per row (garbage rows harmless) */
    {
        int n = r0 + (lane >> 1), hf = lane & 1;
        float* row = &ss[n * 68];
        float mx = -1e30f;
        for (int m = hf; m < NT; m += 2) mx = fmaxf(mx, row[m]);
        mx = fmaxf(mx, __shfl_xor_sync(0xffffffffu, mx, 1));
        float sum = 0.f;
        for (int m = hf; m < NT; m += 2) {
            float e = __expf(row[m] - mx);
            row[m] = e;
            sum += e;
        }
        sum += __shfl_xor_sync(0xffffffffu, sum, 1);
        float inv = 1.0f / sum;
        for (int m = hf; m < NT; m += 2) row[m] *= inv;
    }
    __syncwarp();

    /* write attn probs + build fp16 P rows (cols >= 49 zeroed) */
    {
        float* aout = attn_out + (size_t)(b * HEADS + h) * NT * NT;
        for (int idx = lane; idx < 16 * NT; idx += 32) {
            int r = idx / NT, m = idx - r * NT, n = r0 + r;
            if (n < NT) aout[n * NT + m] = ss[n * 68 + m];
        }
        for (int idx = lane; idx < 16 * 32; idx += 32) {
            int r = idx >> 5, m2 = (idx & 31) << 1, n = r0 + r;
            float v0 = (m2     < NT) ? ss[n * 68 + m2]     : 0.f;
            float v1 = (m2 + 1 < NT) ? ss[n * 68 + m2 + 1] : 0.f;
            *(half2*)&ps[n * 72 + m2] = __floats2half2_rn(v0, v1);
        }
    }
    __syncwarp();

    /* O = P(rows r0..) @ V(64x32), stage to own ss rows, store fp16 */
    {
        wmma::fragment<wmma::accumulator, 16, 16, 16, float> oc[2];
#pragma unroll
        for (int j = 0; j < 2; j++) wmma::fill_fragment(oc[j], 0.0f);
#pragma unroll
        for (int ks = 0; ks < 4; ks++) {
            wmma::fragment<wmma::matrix_a, 16, 16, 16, __half, wmma::row_major> a;
            wmma::load_matrix_sync(a, &ps[r0 * 72 + ks * 16], 72);
#pragma unroll
            for (int j = 0; j < 2; j++) {
                wmma::fragment<wmma::matrix_b, 16, 16, 16, __half, wmma::row_major> bfr;
                wmma::load_matrix_sync(bfr, &vs[(ks * 16) * 40 + j * 16], 40);
                wmma::mma_sync(oc[j], a, bfr, oc[j]);
            }
        }
#pragma unroll
        for (int j = 0; j < 2; j++)
            wmma::store_matrix_sync(&ss[r0 * 68 + j * 16], oc[j], 68,
                                    wmma::mem_row_major);
    }
    __syncwarp();
    {
        __half* obase = o_out + (size_t)b * NT * CDIM + h * HDIM;
        for (int idx = lane; idx < 16 * 16; idx += 32) {
            int r = idx >> 4, d2 = (idx & 15) << 1, n = r0 + r;
            if (n < NT)
                *(half2*)&obase[(size_t)n * CDIM + d2] =
                    __floats2half2_rn(ss[n * 68 + d2], ss[n * 68 + d2 + 1]);
        }
    }
}

/* ===================================================================*/
extern "C" void kernel_launch(void* const* d_in, const int* in_sizes, int n_in,
                              void* d_out, int out_size)
{
    const float* x          = (const float*)d_in[0];
    const float* mask       = (const float*)d_in[1];
    const float* qkv_w      = (const float*)d_in[2];
    const float* qkv_b      = (const float*)d_in[3];
    const float* proj_w     = (const float*)d_in[4];
    const float* proj_b     = (const float*)d_in[5];
    const float* bias_table = (const float*)d_in[6];

    float* out_part  = (float*)d_out;                       /* [200704][256] */
    float* attn_part = out_part + (size_t)MROWS * CDIM;     /* [32768][49][49] */

    __half *xh = nullptr, *qkvh = nullptr, *oh = nullptr, *wh = nullptr, *pwh = nullptr;
    cudaGetSymbolAddress((void**)&xh,   g_xh);
    cudaGetSymbolAddress((void**)&qkvh, g_qkvh);
    cudaGetSymbolAddress((void**)&oh,   g_oh);
    cudaGetSymbolAddress((void**)&wh,   g_wh);
    cudaGetSymbolAddress((void**)&pwh,  g_pwh);

    static int smem_set = 0;
    if (!smem_set) {
        cudaFuncSetAttribute(gemm_h_kernel<1>,
                             cudaFuncAttributeMaxDynamicSharedMemorySize, GEMMH_SMEM);
        cudaFuncSetAttribute(gemm_h_kernel<0>,
                             cudaFuncAttributeMaxDynamicSharedMemorySize, GEMMH_SMEM);
        smem_set = 1;
    }

    /* 0) fp16 conversions */
    f2h_kernel<<<(MROWS * CDIM / 4 + 255) / 256, 256>>>(x, xh, MROWS * CDIM);
    f2h_kernel<<<(KQKV * CDIM / 4 + 255) / 256, 256>>>(qkv_w, wh, KQKV * CDIM);
    f2h_kernel<<<(CDIM * CDIM / 4 + 255) / 256, 256>>>(proj_w, pwh, CDIM * CDIM);

    /* 1) QKV GEMM: [200704,256] @ [768,256]^T + b -> g_qkvh (fp16) */
    gemm_h_kernel<1><<<dim3(KQKV / 128, MROWS / 128), 256, GEMMH_SMEM>>>(
        xh, wh, qkv_b, qkvh, KQKV, CDIM);

    /* 2) per-(window,head) attention */
    attn_kernel<<<dim3(HEADS, B_WIN), 128>>>(
        qkvh, mask, bias_table, attn_part, oh);

    /* 3) proj GEMM: [200704,256] @ [256,256]^T + b -> out (fp32) */
    gemm_h_kernel<0><<<dim3(CDIM / 128, MROWS / 128), 256, GEMMH_SMEM>>>(
        oh, pwh, proj_b, out_part, CDIM, CDIM);
}